// round 11
// baseline (speedup 1.0000x reference)
#include <cuda_runtime.h>

// Problem constants
#define Bn    2
#define Sn    2048
#define En    1024
#define Hn    16
#define DHn   64
#define KSn   3

// ---------------------------------------------------------------------------
// Scratch (device globals; no runtime allocation allowed)
// ---------------------------------------------------------------------------
__device__ float g_Q  [(size_t)Bn * Sn * En];       // [b*S+s][E]
__device__ float g_K  [(size_t)Bn * Sn * En];
__device__ float g_V  [(size_t)Bn * Sn * En];
__device__ float g_ctx[(size_t)Bn * Sn * En];       // attention output pre-Wo
__device__ float g_S  [(size_t)Bn * Hn * Sn * Sn];  // raw scores [bh][q][k]
__device__ float g_S2 [(size_t)Bn * Hn * Sn * Sn];  // softmax weights [bh][q][k]

// ---------------------------------------------------------------------------
// tf32 helpers
// ---------------------------------------------------------------------------
__device__ __forceinline__ float f2tf(float x) {
    unsigned r;
    asm("cvt.rna.tf32.f32 %0, %1;" : "=r"(r) : "f"(x));
    return __uint_as_float(r);
}
__device__ __forceinline__ void stf4(float* p, float4 v) {
    *(float4*)p = make_float4(f2tf(v.x), f2tf(v.y), f2tf(v.z), f2tf(v.w));
}
__device__ __forceinline__ void mma_tf32(
    float& c0, float& c1, float& c2, float& c3,
    unsigned a0, unsigned a1, unsigned a2, unsigned a3,
    unsigned b0, unsigned b1)
{
    asm volatile(
        "mma.sync.aligned.m16n8k8.row.col.f32.tf32.tf32.f32 "
        "{%0,%1,%2,%3}, {%4,%5,%6,%7}, {%8,%9}, {%0,%1,%2,%3};"
        : "+f"(c0), "+f"(c1), "+f"(c2), "+f"(c3)
        : "r"(a0), "r"(a1), "r"(a2), "r"(a3), "r"(b0), "r"(b1));
}

// ---------------------------------------------------------------------------
// fp32 128x128x16 NT GEMM tile (kept for qkv / oproj — exact)
// ---------------------------------------------------------------------------
__device__ __forceinline__ void sgemm_nt_128x128(
    const float* __restrict__ A, int lda,
    const float* __restrict__ B, int ldb,
    float* __restrict__ C, int ldc,
    int K, float alpha, const float* __restrict__ bias)
{
    __shared__ float As[16][128];
    __shared__ float Bs[16][128];

    const int tid = threadIdx.x;
    const int tx  = tid & 15;
    const int ty  = tid >> 4;
    const int lr  = tid >> 2;
    const int lc  = (tid & 3) << 2;

    float acc[8][8];
#pragma unroll
    for (int i = 0; i < 8; ++i)
#pragma unroll
        for (int j = 0; j < 8; ++j) acc[i][j] = 0.f;

    const float* Ap0 = A + (size_t)lr * lda + lc;
    const float* Ap1 = A + (size_t)(lr + 64) * lda + lc;
    const float* Bp0 = B + (size_t)lr * ldb + lc;
    const float* Bp1 = B + (size_t)(lr + 64) * ldb + lc;

    float4 a0 = *(const float4*)(Ap0);
    float4 a1 = *(const float4*)(Ap1);
    float4 b0 = *(const float4*)(Bp0);
    float4 b1 = *(const float4*)(Bp1);

    for (int k0 = 0; k0 < K; k0 += 16) {
        __syncthreads();
        As[lc + 0][lr]      = a0.x; As[lc + 1][lr]      = a0.y;
        As[lc + 2][lr]      = a0.z; As[lc + 3][lr]      = a0.w;
        As[lc + 0][lr + 64] = a1.x; As[lc + 1][lr + 64] = a1.y;
        As[lc + 2][lr + 64] = a1.z; As[lc + 3][lr + 64] = a1.w;
        Bs[lc + 0][lr]      = b0.x; Bs[lc + 1][lr]      = b0.y;
        Bs[lc + 2][lr]      = b0.z; Bs[lc + 3][lr]      = b0.w;
        Bs[lc + 0][lr + 64] = b1.x; Bs[lc + 1][lr + 64] = b1.y;
        Bs[lc + 2][lr + 64] = b1.z; Bs[lc + 3][lr + 64] = b1.w;
        __syncthreads();

        if (k0 + 16 < K) {
            a0 = *(const float4*)(Ap0 + k0 + 16);
            a1 = *(const float4*)(Ap1 + k0 + 16);
            b0 = *(const float4*)(Bp0 + k0 + 16);
            b1 = *(const float4*)(Bp1 + k0 + 16);
        }

#pragma unroll
        for (int k = 0; k < 16; ++k) {
            float4 arl = *(const float4*)&As[k][ty * 8];
            float4 arh = *(const float4*)&As[k][ty * 8 + 4];
            float4 brl = *(const float4*)&Bs[k][tx * 8];
            float4 brh = *(const float4*)&Bs[k][tx * 8 + 4];
            float ar[8] = {arl.x, arl.y, arl.z, arl.w, arh.x, arh.y, arh.z, arh.w};
            float br[8] = {brl.x, brl.y, brl.z, brl.w, brh.x, brh.y, brh.z, brh.w};
#pragma unroll
            for (int i = 0; i < 8; ++i)
#pragma unroll
                for (int j = 0; j < 8; ++j)
                    acc[i][j] = fmaf(ar[i], br[j], acc[i][j]);
        }
    }

    float bv[8];
    if (bias) {
#pragma unroll
        for (int j = 0; j < 8; ++j) bv[j] = bias[tx * 8 + j];
    } else {
#pragma unroll
        for (int j = 0; j < 8; ++j) bv[j] = 0.f;
    }
#pragma unroll
    for (int i = 0; i < 8; ++i) {
        float o[8];
#pragma unroll
        for (int j = 0; j < 8; ++j) o[j] = fmaf(acc[i][j], alpha, bv[j]);
        float* cp = C + (size_t)(ty * 8 + i) * ldc + tx * 8;
        *(float4*)(cp)     = make_float4(o[0], o[1], o[2], o[3]);
        *(float4*)(cp + 4) = make_float4(o[4], o[5], o[6], o[7]);
    }
}

// ---------------------------------------------------------------------------
// Kernel 1: fused QKV projection (fp32 exact). grid (E/128, B*S/128, 3)
// ---------------------------------------------------------------------------
__global__ void __launch_bounds__(256)
qkv_kernel(const float* __restrict__ query,
           const float* __restrict__ Wq, const float* __restrict__ bq,
           const float* __restrict__ Wk, const float* __restrict__ bk,
           const float* __restrict__ Wv, const float* __restrict__ bv)
{
    const int z = blockIdx.z;
    const float* W  = (z == 0) ? Wq : ((z == 1) ? Wk : Wv);
    const float* bi = (z == 0) ? bq : ((z == 1) ? bk : bv);
    float* Cb       = (z == 0) ? g_Q : ((z == 1) ? g_K : g_V);

    const float* A = query + (size_t)blockIdx.y * 128 * En;
    const float* B = W     + (size_t)blockIdx.x * 128 * En;
    float*       C = Cb    + (size_t)blockIdx.y * 128 * En + blockIdx.x * 128;
    sgemm_nt_128x128(A, En, B, En, C, En, En, 1.0f, bi + blockIdx.x * 128);
}

// ---------------------------------------------------------------------------
// Kernel 2: scores = Q K^T / 8 via tf32 mma.sync.  grid (S/128, S/128, B*H)
// 256 threads = 8 warps (2 m-groups x 4 n-groups), warp tile 64x32,
// m16n8k8 fragments. Smem stride 20 -> conflict-free fragment loads.
// ---------------------------------------------------------------------------
__global__ void __launch_bounds__(256)
scores_tf32_kernel()
{
    __shared__ float As[128][20];
    __shared__ float Bs[128][20];

    const int bh = blockIdx.z;
    const int b = bh >> 4, h = bh & 15;
    const float* A = g_Q + ((size_t)b * Sn + blockIdx.y * 128) * En + h * DHn;
    const float* B = g_K + ((size_t)b * Sn + blockIdx.x * 128) * En + h * DHn;
    float*       C = g_S + (size_t)bh * Sn * Sn
                         + (size_t)blockIdx.y * 128 * Sn + blockIdx.x * 128;

    const int tid  = threadIdx.x;
    const int lr   = tid >> 2, lc = (tid & 3) << 2;
    const int wid  = tid >> 5, lane = tid & 31;
    const int wm   = (wid >> 2) * 64, wn = (wid & 3) * 32;
    const int g    = lane >> 2, tg = lane & 3;

    float acc[4][4][4];
#pragma unroll
    for (int mt = 0; mt < 4; ++mt)
#pragma unroll
        for (int nt = 0; nt < 4; ++nt)
#pragma unroll
            for (int c = 0; c < 4; ++c) acc[mt][nt][c] = 0.f;

    const float* Ap0 = A + (size_t)lr * En + lc;
    const float* Ap1 = A + (size_t)(lr + 64) * En + lc;
    const float* Bp0 = B + (size_t)lr * En + lc;
    const float* Bp1 = B + (size_t)(lr + 64) * En + lc;

    float4 a0 = *(const float4*)Ap0;
    float4 a1 = *(const float4*)Ap1;
    float4 b0 = *(const float4*)Bp0;
    float4 b1 = *(const float4*)Bp1;

    for (int k0 = 0; k0 < DHn; k0 += 16) {
        __syncthreads();
        stf4(&As[lr][lc], a0); stf4(&As[lr + 64][lc], a1);
        stf4(&Bs[lr][lc], b0); stf4(&Bs[lr + 64][lc], b1);
        __syncthreads();

        if (k0 + 16 < DHn) {
            a0 = *(const float4*)(Ap0 + k0 + 16);
            a1 = *(const float4*)(Ap1 + k0 + 16);
            b0 = *(const float4*)(Bp0 + k0 + 16);
            b1 = *(const float4*)(Bp1 + k0 + 16);
        }

#pragma unroll
        for (int ks = 0; ks < 2; ++ks) {
            const int kk = ks * 8;
            unsigned af[4][4], bf[4][2];
#pragma unroll
            for (int mt = 0; mt < 4; ++mt) {
                const int r = wm + mt * 16 + g;
                af[mt][0] = __float_as_uint(As[r    ][kk + tg]);
                af[mt][1] = __float_as_uint(As[r + 8][kk + tg]);
                af[mt][2] = __float_as_uint(As[r    ][kk + tg + 4]);
                af[mt][3] = __float_as_uint(As[r + 8][kk + tg + 4]);
            }
#pragma unroll
            for (int nt = 0; nt < 4; ++nt) {
                const int r = wn + nt * 8 + g;
                bf[nt][0] = __float_as_uint(Bs[r][kk + tg]);
                bf[nt][1] = __float_as_uint(Bs[r][kk + tg + 4]);
            }
#pragma unroll
            for (int mt = 0; mt < 4; ++mt)
#pragma unroll
                for (int nt = 0; nt < 4; ++nt)
                    mma_tf32(acc[mt][nt][0], acc[mt][nt][1],
                             acc[mt][nt][2], acc[mt][nt][3],
                             af[mt][0], af[mt][1], af[mt][2], af[mt][3],
                             bf[nt][0], bf[nt][1]);
        }
    }

    const float alpha = 0.125f;
#pragma unroll
    for (int mt = 0; mt < 4; ++mt) {
        const int row = wm + mt * 16 + g;
#pragma unroll
        for (int nt = 0; nt < 4; ++nt) {
            const int col = wn + nt * 8 + tg * 2;
            *(float2*)(C + (size_t)row * Sn + col) =
                make_float2(acc[mt][nt][0] * alpha, acc[mt][nt][1] * alpha);
            *(float2*)(C + (size_t)(row + 8) * Sn + col) =
                make_float2(acc[mt][nt][2] * alpha, acc[mt][nt][3] * alpha);
        }
    }
}

// ---------------------------------------------------------------------------
// Kernel 3: FUSED cross-head conv1d + softmax. One CTA per (b, q).
// All 16 head rows (2048 k + halo) live in dynamic smem; conv computed with
// each thread producing 4 output heads x 16 k from each loaded window
// (lane-staggered h2 -> conflict-free row reads); then per-head softmax via
// warp + smem reduction; normalized weights written once to g_S2.
// Traffic: 0.5 GB read + 0.5 GB write (vs 2 GB for split conv+softmax).
// ---------------------------------------------------------------------------
#define ROWP 2052                       // row stride (mod 32 == 4)
#define FUSED_SMEM_FLOATS (Hn * ROWP + Hn * 49 + Hn + 128)

__global__ void __launch_bounds__(512)
convsoft_kernel(const float* __restrict__ w, const float* __restrict__ cb)
{
    extern __shared__ float dsm[];
    float* rows = dsm;                       // 16 x 2052 (j=k+1, halo at 0 and 2049)
    float* wt   = dsm + Hn * ROWP;           // [h2*49 + h*3 + t], stride 49
    float* cbs  = wt + Hn * 49;              // 16
    float* red  = cbs + Hn;                  // 128

    const int tid = threadIdx.x;
    const int q = blockIdx.x, b = blockIdx.y;

    // weights transposed into [h2][h][t] with row stride 49
    for (int i = tid; i < Hn * Hn * KSn; i += 512) {
        const int h = i / (Hn * KSn);
        const int rem = i - h * (Hn * KSn);
        const int h2 = rem / KSn, t = rem - h2 * KSn;
        wt[h2 * 49 + h * KSn + t] = w[i];
    }
    if (tid < Hn) cbs[tid] = cb[tid];
    if (tid < 32) {                            // zero halos
        const int h = tid >> 1;
        rows[h * ROWP + ((tid & 1) ? 2049 : 0)] = 0.f;
    }

    // load 16 head rows for this (b, q): 16 x 512 float4
#pragma unroll 4
    for (int it = 0; it < 16; ++it) {
        const int idx = tid + it * 512;
        const int h = idx >> 9;
        const int p = idx & 511;
        float4 v = *(const float4*)(g_S + (((size_t)(b * Hn + h) * Sn + q) * Sn) + p * 4);
        float* d = rows + h * ROWP + 1 + p * 4;
        d[0] = v.x; d[1] = v.y; d[2] = v.z; d[3] = v.w;
    }
    __syncthreads();

    const int hg = tid >> 7;      // 0..3 -> heads hg*4 .. hg*4+3
    const int kt = tid & 127;     // 0..127 -> k base kt*16
    const int kb = kt * 16;

    float acc[4][16];
#pragma unroll
    for (int j = 0; j < 4; ++j) {
        const float c0 = cbs[hg * 4 + j];
#pragma unroll
        for (int i = 0; i < 16; ++i) acc[j][i] = c0;
    }

#pragma unroll 1
    for (int hh = 0; hh < Hn; ++hh) {
        const int h2 = (hh + kt) & 15;                 // lane-staggered input head
        const float* r = rows + h2 * ROWP + kb;        // window j = kb .. kb+17
        float win[18];
        float4 t0 = *(const float4*)(r);
        float4 t1 = *(const float4*)(r + 4);
        float4 t2 = *(const float4*)(r + 8);
        float4 t3 = *(const float4*)(r + 12);
        win[0]  = t0.x; win[1]  = t0.y; win[2]  = t0.z; win[3]  = t0.w;
        win[4]  = t1.x; win[5]  = t1.y; win[6]  = t1.z; win[7]  = t1.w;
        win[8]  = t2.x; win[9]  = t2.y; win[10] = t2.z; win[11] = t2.w;
        win[12] = t3.x; win[13] = t3.y; win[14] = t3.z; win[15] = t3.w;
        win[16] = r[16]; win[17] = r[17];

        const float* wp = wt + h2 * 49 + hg * 12;      // h = hg*4+j -> h*3 = hg*12+3j
#pragma unroll
        for (int j = 0; j < 4; ++j) {
            const float w0 = wp[3 * j + 0];
            const float w1 = wp[3 * j + 1];
            const float w2 = wp[3 * j + 2];
#pragma unroll
            for (int i = 0; i < 16; ++i)
                acc[j][i] = fmaf(w0, win[i],
                            fmaf(w1, win[i + 1],
                            fmaf(w2, win[i + 2], acc[j][i])));
        }
    }

    // ---- softmax over k (row = head hg*4+j, distributed over 128 kt threads)
    const int wg = (tid >> 5) & 3;
    const int lane = tid & 31;

    float mx[4];
#pragma unroll
    for (int j = 0; j < 4; ++j) {
        float m = acc[j][0];
#pragma unroll
        for (int i = 1; i < 16; ++i) m = fmaxf(m, acc[j][i]);
#pragma unroll
        for (int o = 16; o > 0; o >>= 1)
            m = fmaxf(m, __shfl_xor_sync(0xffffffffu, m, o));
        mx[j] = m;
    }
    if (lane == 0) {
#pragma unroll
        for (int j = 0; j < 4; ++j) red[(hg * 4 + wg) * 4 + j] = mx[j];
    }
    __syncthreads();

    float mm[4];
#pragma unroll
    for (int j = 0; j < 4; ++j) {
        float m = red[(hg * 4 + 0) * 4 + j];
        m = fmaxf(m, red[(hg * 4 + 1) * 4 + j]);
        m = fmaxf(m, red[(hg * 4 + 2) * 4 + j]);
        m = fmaxf(m, red[(hg * 4 + 3) * 4 + j]);
        mm[j] = m;
    }

    float sm[4];
#pragma unroll
    for (int j = 0; j < 4; ++j) {
        float s = 0.f;
#pragma unroll
        for (int i = 0; i < 16; ++i) {
            acc[j][i] = __expf(acc[j][i] - mm[j]);
            s += acc[j][i];
        }
#pragma unroll
        for (int o = 16; o > 0; o >>= 1)
            s += __shfl_xor_sync(0xffffffffu, s, o);
        sm[j] = s;
    }
    if (lane == 0) {
#pragma unroll
        for (int j = 0; j < 4; ++j) red[64 + (hg * 4 + wg) * 4 + j] = sm[j];
    }
    __syncthreads();

#pragma unroll
    for (int j = 0; j < 4; ++j) {
        const float tot = red[64 + (hg * 4 + 0) * 4 + j]
                        + red[64 + (hg * 4 + 1) * 4 + j]
                        + red[64 + (hg * 4 + 2) * 4 + j]
                        + red[64 + (hg * 4 + 3) * 4 + j];
        const float inv = 1.0f / tot;
        const int h = hg * 4 + j;
        float* dst = g_S2 + (((size_t)(b * Hn + h) * Sn + q) * Sn) + kb;
#pragma unroll
        for (int i = 0; i < 16; i += 4)
            *(float4*)(dst + i) = make_float4(acc[j][i] * inv, acc[j][i + 1] * inv,
                                              acc[j][i + 2] * inv, acc[j][i + 3] * inv);
    }
}

// ---------------------------------------------------------------------------
// Kernel 4: PV via tf32 mma.sync. ctx[q, h*64+d] = sum_k W[q,k] V[k, h*64+d]
// Tile 128(M) x 64(N), 8 warps (2m x 4n), warp tile 64x16. B tile stored
// naturally as Bs[k][n] with stride 72 -> conflict-free fragment loads.
// grid (S/128, B*H)
// ---------------------------------------------------------------------------
__global__ void __launch_bounds__(256)
pv_tf32_kernel()
{
    __shared__ float As[128][20];
    __shared__ float Bs[16][72];

    const int bh = blockIdx.y;
    const int b = bh >> 4, h = bh & 15;
    const float* A  = g_S2 + (size_t)bh * Sn * Sn + (size_t)blockIdx.x * 128 * Sn;
    const float* Bp = g_V  + (size_t)b * Sn * En + h * DHn;
    float*       C  = g_ctx + (size_t)b * Sn * En
                            + (size_t)blockIdx.x * 128 * En + h * DHn;

    const int tid  = threadIdx.x;
    const int lr   = tid >> 2, lc = (tid & 3) << 2;
    const int kr   = tid >> 4, nc = (tid & 15) << 2;
    const int wid  = tid >> 5, lane = tid & 31;
    const int wm   = (wid >> 2) * 64, wn = (wid & 3) * 16;
    const int g    = lane >> 2, tg = lane & 3;

    float acc[4][2][4];
#pragma unroll
    for (int mt = 0; mt < 4; ++mt)
#pragma unroll
        for (int nt = 0; nt < 2; ++nt)
#pragma unroll
            for (int c = 0; c < 4; ++c) acc[mt][nt][c] = 0.f;

    const float* Ap0 = A + (size_t)lr * Sn + lc;
    const float* Ap1 = A + (size_t)(lr + 64) * Sn + lc;
    const float* Bpp = Bp + (size_t)kr * En + nc;

    float4 a0 = *(const float4*)Ap0;
    float4 a1 = *(const float4*)Ap1;
    float4 bb = *(const float4*)Bpp;

    for (int k0 = 0; k0 < Sn; k0 += 16) {
        __syncthreads();
        stf4(&As[lr][lc], a0); stf4(&As[lr + 64][lc], a1);
        stf4(&Bs[kr][nc], bb);
        __syncthreads();

        if (k0 + 16 < Sn) {
            a0 = *(const float4*)(Ap0 + k0 + 16);
            a1 = *(const float4*)(Ap1 + k0 + 16);
            bb = *(const float4*)(Bpp + (size_t)(k0 + 16) * En);
        }

#pragma unroll
        for (int ks = 0; ks < 2; ++ks) {
            const int kk = ks * 8;
            unsigned af[4][4], bf[2][2];
#pragma unroll
            for (int mt = 0; mt < 4; ++mt) {
                const int r = wm + mt * 16 + g;
                af[mt][0] = __float_as_uint(As[r    ][kk + tg]);
                af[mt][1] = __float_as_uint(As[r + 8][kk + tg]);
                af[mt][2] = __float_as_uint(As[r    ][kk + tg + 4]);
                af[mt][3] = __float_as_uint(As[r + 8][kk + tg + 4]);
            }
#pragma unroll
            for (int nt = 0; nt < 2; ++nt) {
                const int n = wn + nt * 8 + g;
                bf[nt][0] = __float_as_uint(Bs[kk + tg    ][n]);
                bf[nt][1] = __float_as_uint(Bs[kk + tg + 4][n]);
            }
#pragma unroll
            for (int mt = 0; mt < 4; ++mt)
#pragma unroll
                for (int nt = 0; nt < 2; ++nt)
                    mma_tf32(acc[mt][nt][0], acc[mt][nt][1],
                             acc[mt][nt][2], acc[mt][nt][3],
                             af[mt][0], af[mt][1], af[mt][2], af[mt][3],
                             bf[nt][0], bf[nt][1]);
        }
    }

#pragma unroll
    for (int mt = 0; mt < 4; ++mt) {
        const int row = wm + mt * 16 + g;
#pragma unroll
        for (int nt = 0; nt < 2; ++nt) {
            const int col = wn + nt * 8 + tg * 2;
            *(float2*)(C + (size_t)row * En + col) =
                make_float2(acc[mt][nt][0], acc[mt][nt][1]);
            *(float2*)(C + (size_t)(row + 8) * En + col) =
                make_float2(acc[mt][nt][2], acc[mt][nt][3]);
        }
    }
}

// ---------------------------------------------------------------------------
// Kernel 5: output projection (fp32 exact): out = ctx @ Wo^T + bo
// ---------------------------------------------------------------------------
__global__ void __launch_bounds__(256)
oproj_kernel(const float* __restrict__ Wo, const float* __restrict__ bo,
             float* __restrict__ out)
{
    const float* A = g_ctx + (size_t)blockIdx.y * 128 * En;
    const float* B = Wo    + (size_t)blockIdx.x * 128 * En;
    float*       C = out   + (size_t)blockIdx.y * 128 * En + blockIdx.x * 128;
    sgemm_nt_128x128(A, En, B, En, C, En, En, 1.0f, bo + blockIdx.x * 128);
}

// ---------------------------------------------------------------------------
// Launch
// ---------------------------------------------------------------------------
extern "C" void kernel_launch(void* const* d_in, const int* in_sizes, int n_in,
                              void* d_out, int out_size)
{
    (void)in_sizes; (void)n_in; (void)out_size;
    const float* query  = (const float*)d_in[0];
    const float* Wq     = (const float*)d_in[1];
    const float* bq     = (const float*)d_in[2];
    const float* Wk     = (const float*)d_in[3];
    const float* bk     = (const float*)d_in[4];
    const float* Wv     = (const float*)d_in[5];
    const float* bv     = (const float*)d_in[6];
    const float* Wo     = (const float*)d_in[7];
    const float* bo     = (const float*)d_in[8];
    const float* conv_w = (const float*)d_in[9];
    const float* conv_b = (const float*)d_in[10];
    float* out = (float*)d_out;

    const int fused_smem = FUSED_SMEM_FLOATS * (int)sizeof(float);
    cudaFuncSetAttribute(convsoft_kernel,
                         cudaFuncAttributeMaxDynamicSharedMemorySize, fused_smem);

    qkv_kernel        <<<dim3(En / 128, (Bn * Sn) / 128, 3), 256>>>(query, Wq, bq, Wk, bk, Wv, bv);
    scores_tf32_kernel<<<dim3(Sn / 128, Sn / 128, Bn * Hn), 256>>>();
    convsoft_kernel   <<<dim3(Sn, Bn), 512, fused_smem>>>(conv_w, conv_b);
    pv_tf32_kernel    <<<dim3(Sn / 128, Bn * Hn), 256>>>();
    oproj_kernel      <<<dim3(En / 128, (Bn * Sn) / 128), 256>>>(Wo, bo, out);
}

// round 12
// speedup vs baseline: 1.0024x; 1.0024x over previous
#include <cuda_runtime.h>

// Problem constants
#define Bn    2
#define Sn    2048
#define En    1024
#define Hn    16
#define DHn   64
#define KSn   3

// ---------------------------------------------------------------------------
// Scratch (device globals; no runtime allocation allowed)
// ---------------------------------------------------------------------------
__device__ float g_Q  [(size_t)Bn * Sn * En];       // [b*S+s][E]
__device__ float g_K  [(size_t)Bn * Sn * En];
__device__ float g_V  [(size_t)Bn * Sn * En];
__device__ float g_ctx[(size_t)Bn * Sn * En];       // attention output pre-Wo
__device__ float g_S  [(size_t)Bn * Hn * Sn * Sn];  // raw scores [bh][q][k]
__device__ float g_S2 [(size_t)Bn * Hn * Sn * Sn];  // softmax weights [bh][q][k]

// ---------------------------------------------------------------------------
// tf32 helpers
// ---------------------------------------------------------------------------
__device__ __forceinline__ float f2tf(float x) {
    unsigned r;
    asm("cvt.rna.tf32.f32 %0, %1;" : "=r"(r) : "f"(x));
    return __uint_as_float(r);
}
__device__ __forceinline__ void stf4(float* p, float4 v) {
    *(float4*)p = make_float4(f2tf(v.x), f2tf(v.y), f2tf(v.z), f2tf(v.w));
}
__device__ __forceinline__ void mma_tf32(
    float& c0, float& c1, float& c2, float& c3,
    unsigned a0, unsigned a1, unsigned a2, unsigned a3,
    unsigned b0, unsigned b1)
{
    asm volatile(
        "mma.sync.aligned.m16n8k8.row.col.f32.tf32.tf32.f32 "
        "{%0,%1,%2,%3}, {%4,%5,%6,%7}, {%8,%9}, {%0,%1,%2,%3};"
        : "+f"(c0), "+f"(c1), "+f"(c2), "+f"(c3)
        : "r"(a0), "r"(a1), "r"(a2), "r"(a3), "r"(b0), "r"(b1));
}

// ---------------------------------------------------------------------------
// fp32 128x128x16 NT GEMM tile (kept for qkv / oproj — exact)
// ---------------------------------------------------------------------------
__device__ __forceinline__ void sgemm_nt_128x128(
    const float* __restrict__ A, int lda,
    const float* __restrict__ B, int ldb,
    float* __restrict__ C, int ldc,
    int K, float alpha, const float* __restrict__ bias)
{
    __shared__ float As[16][128];
    __shared__ float Bs[16][128];

    const int tid = threadIdx.x;
    const int tx  = tid & 15;
    const int ty  = tid >> 4;
    const int lr  = tid >> 2;
    const int lc  = (tid & 3) << 2;

    float acc[8][8];
#pragma unroll
    for (int i = 0; i < 8; ++i)
#pragma unroll
        for (int j = 0; j < 8; ++j) acc[i][j] = 0.f;

    const float* Ap0 = A + (size_t)lr * lda + lc;
    const float* Ap1 = A + (size_t)(lr + 64) * lda + lc;
    const float* Bp0 = B + (size_t)lr * ldb + lc;
    const float* Bp1 = B + (size_t)(lr + 64) * ldb + lc;

    float4 a0 = *(const float4*)(Ap0);
    float4 a1 = *(const float4*)(Ap1);
    float4 b0 = *(const float4*)(Bp0);
    float4 b1 = *(const float4*)(Bp1);

    for (int k0 = 0; k0 < K; k0 += 16) {
        __syncthreads();
        As[lc + 0][lr]      = a0.x; As[lc + 1][lr]      = a0.y;
        As[lc + 2][lr]      = a0.z; As[lc + 3][lr]      = a0.w;
        As[lc + 0][lr + 64] = a1.x; As[lc + 1][lr + 64] = a1.y;
        As[lc + 2][lr + 64] = a1.z; As[lc + 3][lr + 64] = a1.w;
        Bs[lc + 0][lr]      = b0.x; Bs[lc + 1][lr]      = b0.y;
        Bs[lc + 2][lr]      = b0.z; Bs[lc + 3][lr]      = b0.w;
        Bs[lc + 0][lr + 64] = b1.x; Bs[lc + 1][lr + 64] = b1.y;
        Bs[lc + 2][lr + 64] = b1.z; Bs[lc + 3][lr + 64] = b1.w;
        __syncthreads();

        if (k0 + 16 < K) {
            a0 = *(const float4*)(Ap0 + k0 + 16);
            a1 = *(const float4*)(Ap1 + k0 + 16);
            b0 = *(const float4*)(Bp0 + k0 + 16);
            b1 = *(const float4*)(Bp1 + k0 + 16);
        }

#pragma unroll
        for (int k = 0; k < 16; ++k) {
            float4 arl = *(const float4*)&As[k][ty * 8];
            float4 arh = *(const float4*)&As[k][ty * 8 + 4];
            float4 brl = *(const float4*)&Bs[k][tx * 8];
            float4 brh = *(const float4*)&Bs[k][tx * 8 + 4];
            float ar[8] = {arl.x, arl.y, arl.z, arl.w, arh.x, arh.y, arh.z, arh.w};
            float br[8] = {brl.x, brl.y, brl.z, brl.w, brh.x, brh.y, brh.z, brh.w};
#pragma unroll
            for (int i = 0; i < 8; ++i)
#pragma unroll
                for (int j = 0; j < 8; ++j)
                    acc[i][j] = fmaf(ar[i], br[j], acc[i][j]);
        }
    }

    float bv[8];
    if (bias) {
#pragma unroll
        for (int j = 0; j < 8; ++j) bv[j] = bias[tx * 8 + j];
    } else {
#pragma unroll
        for (int j = 0; j < 8; ++j) bv[j] = 0.f;
    }
#pragma unroll
    for (int i = 0; i < 8; ++i) {
        float o[8];
#pragma unroll
        for (int j = 0; j < 8; ++j) o[j] = fmaf(acc[i][j], alpha, bv[j]);
        float* cp = C + (size_t)(ty * 8 + i) * ldc + tx * 8;
        *(float4*)(cp)     = make_float4(o[0], o[1], o[2], o[3]);
        *(float4*)(cp + 4) = make_float4(o[4], o[5], o[6], o[7]);
    }
}

// ---------------------------------------------------------------------------
// Kernel 1: fused QKV projection (fp32 exact). grid (E/128, B*S/128, 3)
// ---------------------------------------------------------------------------
__global__ void __launch_bounds__(256)
qkv_kernel(const float* __restrict__ query,
           const float* __restrict__ Wq, const float* __restrict__ bq,
           const float* __restrict__ Wk, const float* __restrict__ bk,
           const float* __restrict__ Wv, const float* __restrict__ bv)
{
    const int z = blockIdx.z;
    const float* W  = (z == 0) ? Wq : ((z == 1) ? Wk : Wv);
    const float* bi = (z == 0) ? bq : ((z == 1) ? bk : bv);
    float* Cb       = (z == 0) ? g_Q : ((z == 1) ? g_K : g_V);

    const float* A = query + (size_t)blockIdx.y * 128 * En;
    const float* B = W     + (size_t)blockIdx.x * 128 * En;
    float*       C = Cb    + (size_t)blockIdx.y * 128 * En + blockIdx.x * 128;
    sgemm_nt_128x128(A, En, B, En, C, En, En, 1.0f, bi + blockIdx.x * 128);
}

// ---------------------------------------------------------------------------
// Kernel 2: scores = Q K^T / 8 via tf32 mma.sync.  grid (S/128, S/128, B*H)
// 256 threads = 8 warps (2 m-groups x 4 n-groups), warp tile 64x32,
// m16n8k8 fragments. Smem stride 20 -> conflict-free fragment loads.
// ---------------------------------------------------------------------------
__global__ void __launch_bounds__(256)
scores_tf32_kernel()
{
    __shared__ float As[128][20];
    __shared__ float Bs[128][20];

    const int bh = blockIdx.z;
    const int b = bh >> 4, h = bh & 15;
    const float* A = g_Q + ((size_t)b * Sn + blockIdx.y * 128) * En + h * DHn;
    const float* B = g_K + ((size_t)b * Sn + blockIdx.x * 128) * En + h * DHn;
    float*       C = g_S + (size_t)bh * Sn * Sn
                         + (size_t)blockIdx.y * 128 * Sn + blockIdx.x * 128;

    const int tid  = threadIdx.x;
    const int lr   = tid >> 2, lc = (tid & 3) << 2;
    const int wid  = tid >> 5, lane = tid & 31;
    const int wm   = (wid >> 2) * 64, wn = (wid & 3) * 32;
    const int g    = lane >> 2, tg = lane & 3;

    float acc[4][4][4];
#pragma unroll
    for (int mt = 0; mt < 4; ++mt)
#pragma unroll
        for (int nt = 0; nt < 4; ++nt)
#pragma unroll
            for (int c = 0; c < 4; ++c) acc[mt][nt][c] = 0.f;

    const float* Ap0 = A + (size_t)lr * En + lc;
    const float* Ap1 = A + (size_t)(lr + 64) * En + lc;
    const float* Bp0 = B + (size_t)lr * En + lc;
    const float* Bp1 = B + (size_t)(lr + 64) * En + lc;

    float4 a0 = *(const float4*)Ap0;
    float4 a1 = *(const float4*)Ap1;
    float4 b0 = *(const float4*)Bp0;
    float4 b1 = *(const float4*)Bp1;

    for (int k0 = 0; k0 < DHn; k0 += 16) {
        __syncthreads();
        stf4(&As[lr][lc], a0); stf4(&As[lr + 64][lc], a1);
        stf4(&Bs[lr][lc], b0); stf4(&Bs[lr + 64][lc], b1);
        __syncthreads();

        if (k0 + 16 < DHn) {
            a0 = *(const float4*)(Ap0 + k0 + 16);
            a1 = *(const float4*)(Ap1 + k0 + 16);
            b0 = *(const float4*)(Bp0 + k0 + 16);
            b1 = *(const float4*)(Bp1 + k0 + 16);
        }

#pragma unroll
        for (int ks = 0; ks < 2; ++ks) {
            const int kk = ks * 8;
            unsigned af[4][4], bf[4][2];
#pragma unroll
            for (int mt = 0; mt < 4; ++mt) {
                const int r = wm + mt * 16 + g;
                af[mt][0] = __float_as_uint(As[r    ][kk + tg]);
                af[mt][1] = __float_as_uint(As[r + 8][kk + tg]);
                af[mt][2] = __float_as_uint(As[r    ][kk + tg + 4]);
                af[mt][3] = __float_as_uint(As[r + 8][kk + tg + 4]);
            }
#pragma unroll
            for (int nt = 0; nt < 4; ++nt) {
                const int r = wn + nt * 8 + g;
                bf[nt][0] = __float_as_uint(Bs[r][kk + tg]);
                bf[nt][1] = __float_as_uint(Bs[r][kk + tg + 4]);
            }
#pragma unroll
            for (int mt = 0; mt < 4; ++mt)
#pragma unroll
                for (int nt = 0; nt < 4; ++nt)
                    mma_tf32(acc[mt][nt][0], acc[mt][nt][1],
                             acc[mt][nt][2], acc[mt][nt][3],
                             af[mt][0], af[mt][1], af[mt][2], af[mt][3],
                             bf[nt][0], bf[nt][1]);
        }
    }

    const float alpha = 0.125f;
#pragma unroll
    for (int mt = 0; mt < 4; ++mt) {
        const int row = wm + mt * 16 + g;
#pragma unroll
        for (int nt = 0; nt < 4; ++nt) {
            const int col = wn + nt * 8 + tg * 2;
            *(float2*)(C + (size_t)row * Sn + col) =
                make_float2(acc[mt][nt][0] * alpha, acc[mt][nt][1] * alpha);
            *(float2*)(C + (size_t)(row + 8) * Sn + col) =
                make_float2(acc[mt][nt][2] * alpha, acc[mt][nt][3] * alpha);
        }
    }
}

// ---------------------------------------------------------------------------
// Kernel 3: FUSED cross-head conv1d + softmax. One CTA per (b, q).
// All 16 head rows (2048 k + halo) live in dynamic smem; conv computed with
// each thread producing 4 output heads x 16 k from each loaded window
// (lane-staggered h2 -> conflict-free row reads); then per-head softmax via
// warp + smem reduction; normalized weights written once to g_S2.
// Traffic: 0.5 GB read + 0.5 GB write (vs 2 GB for split conv+softmax).
// ---------------------------------------------------------------------------
#define ROWP 2052                       // row stride (mod 32 == 4)
#define FUSED_SMEM_FLOATS (Hn * ROWP + Hn * 49 + Hn + 128)

__global__ void __launch_bounds__(512)
convsoft_kernel(const float* __restrict__ w, const float* __restrict__ cb)
{
    extern __shared__ float dsm[];
    float* rows = dsm;                       // 16 x 2052 (j=k+1, halo at 0 and 2049)
    float* wt   = dsm + Hn * ROWP;           // [h2*49 + h*3 + t], stride 49
    float* cbs  = wt + Hn * 49;              // 16
    float* red  = cbs + Hn;                  // 128

    const int tid = threadIdx.x;
    const int q = blockIdx.x, b = blockIdx.y;

    // weights transposed into [h2][h][t] with row stride 49
    for (int i = tid; i < Hn * Hn * KSn; i += 512) {
        const int h = i / (Hn * KSn);
        const int rem = i - h * (Hn * KSn);
        const int h2 = rem / KSn, t = rem - h2 * KSn;
        wt[h2 * 49 + h * KSn + t] = w[i];
    }
    if (tid < Hn) cbs[tid] = cb[tid];
    if (tid < 32) {                            // zero halos
        const int h = tid >> 1;
        rows[h * ROWP + ((tid & 1) ? 2049 : 0)] = 0.f;
    }

    // load 16 head rows for this (b, q): 16 x 512 float4
#pragma unroll 4
    for (int it = 0; it < 16; ++it) {
        const int idx = tid + it * 512;
        const int h = idx >> 9;
        const int p = idx & 511;
        float4 v = *(const float4*)(g_S + (((size_t)(b * Hn + h) * Sn + q) * Sn) + p * 4);
        float* d = rows + h * ROWP + 1 + p * 4;
        d[0] = v.x; d[1] = v.y; d[2] = v.z; d[3] = v.w;
    }
    __syncthreads();

    const int hg = tid >> 7;      // 0..3 -> heads hg*4 .. hg*4+3
    const int kt = tid & 127;     // 0..127 -> k base kt*16
    const int kb = kt * 16;

    float acc[4][16];
#pragma unroll
    for (int j = 0; j < 4; ++j) {
        const float c0 = cbs[hg * 4 + j];
#pragma unroll
        for (int i = 0; i < 16; ++i) acc[j][i] = c0;
    }

#pragma unroll 1
    for (int hh = 0; hh < Hn; ++hh) {
        const int h2 = (hh + kt) & 15;                 // lane-staggered input head
        const float* r = rows + h2 * ROWP + kb;        // window j = kb .. kb+17
        float win[18];
        float4 t0 = *(const float4*)(r);
        float4 t1 = *(const float4*)(r + 4);
        float4 t2 = *(const float4*)(r + 8);
        float4 t3 = *(const float4*)(r + 12);
        win[0]  = t0.x; win[1]  = t0.y; win[2]  = t0.z; win[3]  = t0.w;
        win[4]  = t1.x; win[5]  = t1.y; win[6]  = t1.z; win[7]  = t1.w;
        win[8]  = t2.x; win[9]  = t2.y; win[10] = t2.z; win[11] = t2.w;
        win[12] = t3.x; win[13] = t3.y; win[14] = t3.z; win[15] = t3.w;
        win[16] = r[16]; win[17] = r[17];

        const float* wp = wt + h2 * 49 + hg * 12;      // h = hg*4+j -> h*3 = hg*12+3j
#pragma unroll
        for (int j = 0; j < 4; ++j) {
            const float w0 = wp[3 * j + 0];
            const float w1 = wp[3 * j + 1];
            const float w2 = wp[3 * j + 2];
#pragma unroll
            for (int i = 0; i < 16; ++i)
                acc[j][i] = fmaf(w0, win[i],
                            fmaf(w1, win[i + 1],
                            fmaf(w2, win[i + 2], acc[j][i])));
        }
    }

    // ---- softmax over k (row = head hg*4+j, distributed over 128 kt threads)
    const int wg = (tid >> 5) & 3;
    const int lane = tid & 31;

    float mx[4];
#pragma unroll
    for (int j = 0; j < 4; ++j) {
        float m = acc[j][0];
#pragma unroll
        for (int i = 1; i < 16; ++i) m = fmaxf(m, acc[j][i]);
#pragma unroll
        for (int o = 16; o > 0; o >>= 1)
            m = fmaxf(m, __shfl_xor_sync(0xffffffffu, m, o));
        mx[j] = m;
    }
    if (lane == 0) {
#pragma unroll
        for (int j = 0; j < 4; ++j) red[(hg * 4 + wg) * 4 + j] = mx[j];
    }
    __syncthreads();

    float mm[4];
#pragma unroll
    for (int j = 0; j < 4; ++j) {
        float m = red[(hg * 4 + 0) * 4 + j];
        m = fmaxf(m, red[(hg * 4 + 1) * 4 + j]);
        m = fmaxf(m, red[(hg * 4 + 2) * 4 + j]);
        m = fmaxf(m, red[(hg * 4 + 3) * 4 + j]);
        mm[j] = m;
    }

    float sm[4];
#pragma unroll
    for (int j = 0; j < 4; ++j) {
        float s = 0.f;
#pragma unroll
        for (int i = 0; i < 16; ++i) {
            acc[j][i] = __expf(acc[j][i] - mm[j]);
            s += acc[j][i];
        }
#pragma unroll
        for (int o = 16; o > 0; o >>= 1)
            s += __shfl_xor_sync(0xffffffffu, s, o);
        sm[j] = s;
    }
    if (lane == 0) {
#pragma unroll
        for (int j = 0; j < 4; ++j) red[64 + (hg * 4 + wg) * 4 + j] = sm[j];
    }
    __syncthreads();

#pragma unroll
    for (int j = 0; j < 4; ++j) {
        const float tot = red[64 + (hg * 4 + 0) * 4 + j]
                        + red[64 + (hg * 4 + 1) * 4 + j]
                        + red[64 + (hg * 4 + 2) * 4 + j]
                        + red[64 + (hg * 4 + 3) * 4 + j];
        const float inv = 1.0f / tot;
        const int h = hg * 4 + j;
        float* dst = g_S2 + (((size_t)(b * Hn + h) * Sn + q) * Sn) + kb;
#pragma unroll
        for (int i = 0; i < 16; i += 4)
            *(float4*)(dst + i) = make_float4(acc[j][i] * inv, acc[j][i + 1] * inv,
                                              acc[j][i + 2] * inv, acc[j][i + 3] * inv);
    }
}

// ---------------------------------------------------------------------------
// Kernel 4: PV via tf32 mma.sync. ctx[q, h*64+d] = sum_k W[q,k] V[k, h*64+d]
// Tile 128(M) x 64(N), 8 warps (2m x 4n), warp tile 64x16. B tile stored
// naturally as Bs[k][n] with stride 72 -> conflict-free fragment loads.
// grid (S/128, B*H)
// ---------------------------------------------------------------------------
__global__ void __launch_bounds__(256)
pv_tf32_kernel()
{
    __shared__ float As[128][20];
    __shared__ float Bs[16][72];

    const int bh = blockIdx.y;
    const int b = bh >> 4, h = bh & 15;
    const float* A  = g_S2 + (size_t)bh * Sn * Sn + (size_t)blockIdx.x * 128 * Sn;
    const float* Bp = g_V  + (size_t)b * Sn * En + h * DHn;
    float*       C  = g_ctx + (size_t)b * Sn * En
                            + (size_t)blockIdx.x * 128 * En + h * DHn;

    const int tid  = threadIdx.x;
    const int lr   = tid >> 2, lc = (tid & 3) << 2;
    const int kr   = tid >> 4, nc = (tid & 15) << 2;
    const int wid  = tid >> 5, lane = tid & 31;
    const int wm   = (wid >> 2) * 64, wn = (wid & 3) * 16;
    const int g    = lane >> 2, tg = lane & 3;

    float acc[4][2][4];
#pragma unroll
    for (int mt = 0; mt < 4; ++mt)
#pragma unroll
        for (int nt = 0; nt < 2; ++nt)
#pragma unroll
            for (int c = 0; c < 4; ++c) acc[mt][nt][c] = 0.f;

    const float* Ap0 = A + (size_t)lr * Sn + lc;
    const float* Ap1 = A + (size_t)(lr + 64) * Sn + lc;
    const float* Bpp = Bp + (size_t)kr * En + nc;

    float4 a0 = *(const float4*)Ap0;
    float4 a1 = *(const float4*)Ap1;
    float4 bb = *(const float4*)Bpp;

    for (int k0 = 0; k0 < Sn; k0 += 16) {
        __syncthreads();
        stf4(&As[lr][lc], a0); stf4(&As[lr + 64][lc], a1);
        stf4(&Bs[kr][nc], bb);
        __syncthreads();

        if (k0 + 16 < Sn) {
            a0 = *(const float4*)(Ap0 + k0 + 16);
            a1 = *(const float4*)(Ap1 + k0 + 16);
            bb = *(const float4*)(Bpp + (size_t)(k0 + 16) * En);
        }

#pragma unroll
        for (int ks = 0; ks < 2; ++ks) {
            const int kk = ks * 8;
            unsigned af[4][4], bf[2][2];
#pragma unroll
            for (int mt = 0; mt < 4; ++mt) {
                const int r = wm + mt * 16 + g;
                af[mt][0] = __float_as_uint(As[r    ][kk + tg]);
                af[mt][1] = __float_as_uint(As[r + 8][kk + tg]);
                af[mt][2] = __float_as_uint(As[r    ][kk + tg + 4]);
                af[mt][3] = __float_as_uint(As[r + 8][kk + tg + 4]);
            }
#pragma unroll
            for (int nt = 0; nt < 2; ++nt) {
                const int n = wn + nt * 8 + g;
                bf[nt][0] = __float_as_uint(Bs[kk + tg    ][n]);
                bf[nt][1] = __float_as_uint(Bs[kk + tg + 4][n]);
            }
#pragma unroll
            for (int mt = 0; mt < 4; ++mt)
#pragma unroll
                for (int nt = 0; nt < 2; ++nt)
                    mma_tf32(acc[mt][nt][0], acc[mt][nt][1],
                             acc[mt][nt][2], acc[mt][nt][3],
                             af[mt][0], af[mt][1], af[mt][2], af[mt][3],
                             bf[nt][0], bf[nt][1]);
        }
    }

#pragma unroll
    for (int mt = 0; mt < 4; ++mt) {
        const int row = wm + mt * 16 + g;
#pragma unroll
        for (int nt = 0; nt < 2; ++nt) {
            const int col = wn + nt * 8 + tg * 2;
            *(float2*)(C + (size_t)row * En + col) =
                make_float2(acc[mt][nt][0], acc[mt][nt][1]);
            *(float2*)(C + (size_t)(row + 8) * En + col) =
                make_float2(acc[mt][nt][2], acc[mt][nt][3]);
        }
    }
}

// ---------------------------------------------------------------------------
// Kernel 5: output projection (fp32 exact): out = ctx @ Wo^T + bo
// ---------------------------------------------------------------------------
__global__ void __launch_bounds__(256)
oproj_kernel(const float* __restrict__ Wo, const float* __restrict__ bo,
             float* __restrict__ out)
{
    const float* A = g_ctx + (size_t)blockIdx.y * 128 * En;
    const float* B = Wo    + (size_t)blockIdx.x * 128 * En;
    float*       C = out   + (size_t)blockIdx.y * 128 * En + blockIdx.x * 128;
    sgemm_nt_128x128(A, En, B, En, C, En, En, 1.0f, bo + blockIdx.x * 128);
}

// ---------------------------------------------------------------------------
// Launch
// ---------------------------------------------------------------------------
extern "C" void kernel_launch(void* const* d_in, const int* in_sizes, int n_in,
                              void* d_out, int out_size)
{
    (void)in_sizes; (void)n_in; (void)out_size;
    const float* query  = (const float*)d_in[0];
    const float* Wq     = (const float*)d_in[1];
    const float* bq     = (const float*)d_in[2];
    const float* Wk     = (const float*)d_in[3];
    const float* bk     = (const float*)d_in[4];
    const float* Wv     = (const float*)d_in[5];
    const float* bv     = (const float*)d_in[6];
    const float* Wo     = (const float*)d_in[7];
    const float* bo     = (const float*)d_in[8];
    const float* conv_w = (const float*)d_in[9];
    const float* conv_b = (const float*)d_in[10];
    float* out = (float*)d_out;

    const int fused_smem = FUSED_SMEM_FLOATS * (int)sizeof(float);
    cudaFuncSetAttribute(convsoft_kernel,
                         cudaFuncAttributeMaxDynamicSharedMemorySize, fused_smem);

    qkv_kernel        <<<dim3(En / 128, (Bn * Sn) / 128, 3), 256>>>(query, Wq, bq, Wk, bk, Wv, bv);
    scores_tf32_kernel<<<dim3(Sn / 128, Sn / 128, Bn * Hn), 256>>>();
    convsoft_kernel   <<<dim3(Sn, Bn), 512, fused_smem>>>(conv_w, conv_b);
    pv_tf32_kernel    <<<dim3(Sn / 128, Bn * Hn), 256>>>();
    oproj_kernel      <<<dim3(En / 128, (Bn * Sn) / 128), 256>>>(Wo, bo, out);
}